// round 1
// baseline (speedup 1.0000x reference)
#include <cuda_runtime.h>

#define BATCH 4
#define DIMC 256
#define MIDC 128
#define HH 128
#define WW 128
#define EPSV 1e-5f

// Scratch (device globals: allocation-free)
__device__ float g_colmax[BATCH * MIDC * WW];   // max over h of branch1
__device__ float g_rowmax[BATCH * MIDC * HH];   // max over w of branch2
__device__ float g_r[(size_t)BATCH * DIMC * HH * WW];  // relu(p_bn1 + bn1)

__global__ void init_max_kernel() {
    int i = blockIdx.x * blockDim.x + threadIdx.x;
    if (i < BATCH * MIDC * WW) {
        g_colmax[i] = 0.f;
        g_rowmax[i] = 0.f;
    }
}

// Generic 3x3 conv (pad=1) + BN + ReLU.
// mode 0: reduce max over h -> out (as colmax, int-bits atomics)
// mode 1: reduce max over w -> out (as rowmax)
// mode 2: store result to out (NCHW, COUT channels = gridDim.y*8)
__global__ __launch_bounds__(128)
void conv3_kernel(const float* __restrict__ in, const float* __restrict__ wgt,
                  const float* __restrict__ gamma, const float* __restrict__ beta,
                  const float* __restrict__ mean, const float* __restrict__ var,
                  int CIN, int COUT, int mode, float* __restrict__ out)
{
    __shared__ float sIn[4][10][66];
    __shared__ float sW[8][4][9];
    __shared__ float sSc[8], sSh[8];
    __shared__ int sMax[8][64];

    const int tw = blockIdx.x & 1, th = blockIdx.x >> 1;
    const int w0 = tw * 64, h0 = th * 8;
    const int co0 = blockIdx.y * 8;
    const int b = blockIdx.z;
    const int xx = threadIdx.x, yy = threadIdx.y;
    const int tid = yy * 16 + xx;

    if (tid < 8) {
        int c = co0 + tid;
        float sc = gamma[c] * rsqrtf(var[c] + EPSV);
        sSc[tid] = sc;
        sSh[tid] = beta[c] - mean[c] * sc;
    }
    for (int i = tid; i < 512; i += 128) ((int*)sMax)[i] = 0;
    __syncthreads();

    float acc[8][4];
#pragma unroll
    for (int co = 0; co < 8; co++)
#pragma unroll
        for (int p = 0; p < 4; p++) acc[co][p] = 0.f;

    const float* inb = in + (size_t)b * CIN * HH * WW;

    for (int ci0 = 0; ci0 < CIN; ci0 += 4) {
        // input tile: 4 ci x 10 rows x 66 cols (with halo)
        for (int idx = tid; idx < 2640; idx += 128) {
            int ci = idx / 660, rem = idx % 660;
            int hh = rem / 66, wl = rem % 66;
            int gh = h0 - 1 + hh, gw = w0 - 1 + wl;
            float v = 0.f;
            if (gh >= 0 && gh < HH && gw >= 0 && gw < WW)
                v = inb[(size_t)(ci0 + ci) * HH * WW + gh * WW + gw];
            sIn[ci][hh][wl] = v;
        }
        // weights, pre-scaled by BN scale
        for (int idx = tid; idx < 288; idx += 128) {
            int co = idx / 36, rem = idx % 36, ci = rem / 9, k = rem % 9;
            sW[co][ci][k] = wgt[((size_t)(co0 + co) * CIN + ci0 + ci) * 9 + k] * sSc[co];
        }
        __syncthreads();
#pragma unroll
        for (int ci = 0; ci < 4; ci++) {
#pragma unroll
            for (int dy = 0; dy < 3; dy++) {
#pragma unroll
                for (int dx = 0; dx < 3; dx++) {
                    float iv[4];
#pragma unroll
                    for (int p = 0; p < 4; p++)
                        iv[p] = sIn[ci][yy + dy][xx + 16 * p + dx];
#pragma unroll
                    for (int co = 0; co < 8; co++) {
                        float wv = sW[co][ci][dy * 3 + dx];
#pragma unroll
                        for (int p = 0; p < 4; p++)
                            acc[co][p] = fmaf(wv, iv[p], acc[co][p]);
                    }
                }
            }
        }
        __syncthreads();
    }

    if (mode == 2) {
#pragma unroll
        for (int co = 0; co < 8; co++)
#pragma unroll
            for (int p = 0; p < 4; p++) {
                float y = fmaxf(acc[co][p] + sSh[co], 0.f);
                out[((size_t)(b * COUT + co0 + co) * HH + h0 + yy) * WW + w0 + xx + 16 * p] = y;
            }
    } else {
#pragma unroll
        for (int co = 0; co < 8; co++)
#pragma unroll
            for (int p = 0; p < 4; p++) {
                float y = fmaxf(acc[co][p] + sSh[co], 0.f);
                int bits = __float_as_int(y);  // y >= 0 -> monotone int compare
                if (mode == 0) atomicMax(&sMax[co][xx + 16 * p], bits);
                else           atomicMax(&sMax[co][yy], bits);
            }
        __syncthreads();
        int* gout = (int*)out;
        if (mode == 0) {
            for (int i = tid; i < 512; i += 128) {
                int co = i >> 6, w = i & 63;
                atomicMax(&gout[(b * MIDC + co0 + co) * WW + w0 + w], sMax[co][w]);
            }
        } else {
            if (tid < 64) {
                int co = tid >> 3, h = tid & 7;
                atomicMax(&gout[(b * MIDC + co0 + co) * HH + h0 + h], sMax[co][h]);
            }
        }
    }
}

// Fused merge: r = relu( bn_p(conv3x3(s, p_w)) + bn_c1(conv1x1(x, c1_w)) )
// where s[b,c,h,w] = colmax[b,c,w] + rowmax[b,c,h] (zero outside bounds).
__global__ __launch_bounds__(128)
void merge_kernel(const float* __restrict__ x,
                  const float* __restrict__ pw, const float* __restrict__ pg,
                  const float* __restrict__ pb, const float* __restrict__ pm,
                  const float* __restrict__ pv,
                  const float* __restrict__ c1w, const float* __restrict__ c1g,
                  const float* __restrict__ c1b, const float* __restrict__ c1m,
                  const float* __restrict__ c1v)
{
    __shared__ float sCm[4][66];
    __shared__ float sRm[4][10];
    __shared__ float sW3[8][4][9];
    __shared__ float sIn1[4][8][65];
    __shared__ float sW1[8][4];
    __shared__ float sScP[8], sScC[8], sSh[8];

    const int tw = blockIdx.x & 1, th = blockIdx.x >> 1;
    const int w0 = tw * 64, h0 = th * 8;
    const int co0 = blockIdx.y * 8;
    const int b = blockIdx.z;
    const int xx = threadIdx.x, yy = threadIdx.y;
    const int tid = yy * 16 + xx;

    if (tid < 8) {
        int c = co0 + tid;
        float scp = pg[c] * rsqrtf(pv[c] + EPSV);
        float scc = c1g[c] * rsqrtf(c1v[c] + EPSV);
        sScP[tid] = scp;
        sScC[tid] = scc;
        sSh[tid] = (pb[c] - pm[c] * scp) + (c1b[c] - c1m[c] * scc);
    }
    __syncthreads();

    float acc[8][4];
#pragma unroll
    for (int co = 0; co < 8; co++)
#pragma unroll
        for (int p = 0; p < 4; p++) acc[co][p] = 0.f;

    // ---- Phase A: 1x1 conv over x (DIMC channels), weights pre-scaled by c1 bn scale
    const float* xb = x + (size_t)b * DIMC * HH * WW;
    for (int ci0 = 0; ci0 < DIMC; ci0 += 4) {
        for (int idx = tid; idx < 2048; idx += 128) {
            int ci = idx >> 9, rem = idx & 511;
            int hh = rem >> 6, wl = rem & 63;
            sIn1[ci][hh][wl] = xb[(size_t)(ci0 + ci) * HH * WW + (h0 + hh) * WW + w0 + wl];
        }
        if (tid < 32) {
            int co = tid >> 2, ci = tid & 3;
            sW1[co][ci] = c1w[(size_t)(co0 + co) * DIMC + ci0 + ci] * sScC[co];
        }
        __syncthreads();
#pragma unroll
        for (int ci = 0; ci < 4; ci++) {
            float iv[4];
#pragma unroll
            for (int p = 0; p < 4; p++) iv[p] = sIn1[ci][yy][xx + 16 * p];
#pragma unroll
            for (int co = 0; co < 8; co++) {
                float wv = sW1[co][ci];
#pragma unroll
                for (int p = 0; p < 4; p++) acc[co][p] = fmaf(wv, iv[p], acc[co][p]);
            }
        }
        __syncthreads();
    }

    // ---- Phase B: 3x3 conv over s (MIDC channels), s built on the fly
    for (int ci0 = 0; ci0 < MIDC; ci0 += 4) {
        for (int idx = tid; idx < 264; idx += 128) {
            int ci = idx / 66, wl = idx % 66;
            int gw = w0 - 1 + wl;
            sCm[ci][wl] = (gw >= 0 && gw < WW) ? g_colmax[(b * MIDC + ci0 + ci) * WW + gw] : 0.f;
        }
        for (int idx = tid; idx < 40; idx += 128) {
            int ci = idx / 10, hh = idx % 10;
            int gh = h0 - 1 + hh;
            sRm[ci][hh] = (gh >= 0 && gh < HH) ? g_rowmax[(b * MIDC + ci0 + ci) * HH + gh] : 0.f;
        }
        for (int idx = tid; idx < 288; idx += 128) {
            int co = idx / 36, rem = idx % 36, ci = rem / 9, k = rem % 9;
            sW3[co][ci][k] = pw[((size_t)(co0 + co) * MIDC + ci0 + ci) * 9 + k] * sScP[co];
        }
        __syncthreads();
#pragma unroll
        for (int ci = 0; ci < 4; ci++) {
#pragma unroll
            for (int dy = 0; dy < 3; dy++) {
                bool vh = (unsigned)(h0 + yy + dy - 1) < (unsigned)HH;
                float rmv = sRm[ci][yy + dy];
#pragma unroll
                for (int dx = 0; dx < 3; dx++) {
                    float iv[4];
#pragma unroll
                    for (int p = 0; p < 4; p++) {
                        int wl = xx + 16 * p + dx;
                        bool vw = (unsigned)(w0 + wl - 1) < (unsigned)WW;
                        iv[p] = (vh && vw) ? (sCm[ci][wl] + rmv) : 0.f;
                    }
#pragma unroll
                    for (int co = 0; co < 8; co++) {
                        float wv = sW3[co][ci][dy * 3 + dx];
#pragma unroll
                        for (int p = 0; p < 4; p++)
                            acc[co][p] = fmaf(wv, iv[p], acc[co][p]);
                    }
                }
            }
        }
        __syncthreads();
    }

    // epilogue: residual-summed BN shift + ReLU
#pragma unroll
    for (int co = 0; co < 8; co++)
#pragma unroll
        for (int p = 0; p < 4; p++) {
            float y = fmaxf(acc[co][p] + sSh[co], 0.f);
            g_r[((size_t)(b * DIMC + co0 + co) * HH + h0 + yy) * WW + w0 + xx + 16 * p] = y;
        }
}

extern "C" void kernel_launch(void* const* d_in, const int* in_sizes, int n_in,
                              void* d_out, int out_size)
{
    const float* x    = (const float*)d_in[0];
    const float* p1w  = (const float*)d_in[1];
    const float* p1g  = (const float*)d_in[2];
    const float* p1b  = (const float*)d_in[3];
    const float* p1m  = (const float*)d_in[4];
    const float* p1v  = (const float*)d_in[5];
    const float* p2w  = (const float*)d_in[6];
    const float* p2g  = (const float*)d_in[7];
    const float* p2b  = (const float*)d_in[8];
    const float* p2m  = (const float*)d_in[9];
    const float* p2v  = (const float*)d_in[10];
    const float* pw   = (const float*)d_in[11];
    const float* pg   = (const float*)d_in[12];
    const float* pb   = (const float*)d_in[13];
    const float* pm   = (const float*)d_in[14];
    const float* pv   = (const float*)d_in[15];
    const float* c1w  = (const float*)d_in[16];
    const float* c1g  = (const float*)d_in[17];
    const float* c1b  = (const float*)d_in[18];
    const float* c1m  = (const float*)d_in[19];
    const float* c1v  = (const float*)d_in[20];
    const float* c2w  = (const float*)d_in[21];
    const float* c2g  = (const float*)d_in[22];
    const float* c2b  = (const float*)d_in[23];
    const float* c2m  = (const float*)d_in[24];
    const float* c2v  = (const float*)d_in[25];

    float* colmax;  cudaGetSymbolAddress((void**)&colmax, g_colmax);
    float* rowmax;  cudaGetSymbolAddress((void**)&rowmax, g_rowmax);
    float* rbuf;    cudaGetSymbolAddress((void**)&rbuf, g_r);

    dim3 blk(16, 8);

    // 1) zero the max buffers
    init_max_kernel<<<256, 256>>>();

    // 2) branch 1: conv-bn-relu + column max (over h)
    conv3_kernel<<<dim3(32, MIDC / 8, BATCH), blk>>>(
        x, p1w, p1g, p1b, p1m, p1v, DIMC, MIDC, 0, colmax);

    // 3) branch 2: conv-bn-relu + row max (over w)
    conv3_kernel<<<dim3(32, MIDC / 8, BATCH), blk>>>(
        x, p2w, p2g, p2b, p2m, p2v, DIMC, MIDC, 1, rowmax);

    // 4) fused merge: conv3x3(s) bn + conv1x1(x) bn + add + relu -> g_r
    merge_kernel<<<dim3(32, DIMC / 8, BATCH), blk>>>(
        x, pw, pg, pb, pm, pv, c1w, c1g, c1b, c1m, c1v);

    // 5) final conv-bn-relu -> d_out
    conv3_kernel<<<dim3(32, DIMC / 8, BATCH), blk>>>(
        rbuf, c2w, c2g, c2b, c2m, c2v, DIMC, DIMC, 2, (float*)d_out);
}

// round 2
// speedup vs baseline: 1.0327x; 1.0327x over previous
#include <cuda_runtime.h>

#define BATCH 4
#define DIMC 256
#define MIDC 128
#define HH 128
#define WW 128
#define EPSV 1e-5f

typedef unsigned long long u64;

__device__ __forceinline__ u64 pack2(float lo, float hi) {
    u64 r;
    asm("mov.b64 %0, {%1, %2};" : "=l"(r) : "f"(lo), "f"(hi));
    return r;
}
__device__ __forceinline__ void unpack2(u64 v, float& lo, float& hi) {
    asm("mov.b64 {%0, %1}, %2;" : "=f"(lo), "=f"(hi) : "l"(v));
}
__device__ __forceinline__ void fma2(u64& d, u64 a, u64 b) {
    asm("fma.rn.f32x2 %0, %1, %2, %0;" : "+l"(d) : "l"(a), "l"(b));
}

// Scratch (device globals: allocation-free)
__device__ float g_colmax[BATCH * MIDC * WW];   // max over h of branch1
__device__ float g_rowmax[BATCH * MIDC * HH];   // max over w of branch2
__device__ float g_r[(size_t)BATCH * DIMC * HH * WW];  // relu(p_bn1 + bn1)

__global__ void init_max_kernel() {
    int i = blockIdx.x * blockDim.x + threadIdx.x;
    if (i < BATCH * MIDC * WW) {
        g_colmax[i] = 0.f;
        g_rowmax[i] = 0.f;
    }
}

// Generic 3x3 conv (pad=1) + BN + ReLU, packed-f32x2 math.
// mode 0: reduce max over h -> out (colmax, int-bits atomics)
// mode 1: reduce max over w -> out (rowmax)
// mode 2: store result to out (NCHW)
__global__ __launch_bounds__(128)
void conv3_kernel(const float* __restrict__ in, const float* __restrict__ wgt,
                  const float* __restrict__ gamma, const float* __restrict__ beta,
                  const float* __restrict__ mean, const float* __restrict__ var,
                  int CIN, int COUT, int mode, float* __restrict__ out)
{
    __shared__ float sIn[4][10][66];
    __shared__ u64 sW[8][4][9];        // BN-scaled weights, duplicated halves
    __shared__ float sSc[8], sSh[8];
    __shared__ int sMax[8][64];

    const int tw = blockIdx.x & 1, th = blockIdx.x >> 1;
    const int w0 = tw * 64, h0 = th * 8;
    const int co0 = blockIdx.y * 8;
    const int b = blockIdx.z;
    const int xx = threadIdx.x, yy = threadIdx.y;
    const int tid = yy * 16 + xx;

    if (tid < 8) {
        int c = co0 + tid;
        float sc = gamma[c] * rsqrtf(var[c] + EPSV);
        sSc[tid] = sc;
        sSh[tid] = beta[c] - mean[c] * sc;
    }
    for (int i = tid; i < 512; i += 128) ((int*)sMax)[i] = 0;
    __syncthreads();

    u64 acc[8][2];
#pragma unroll
    for (int co = 0; co < 8; co++) { acc[co][0] = 0ULL; acc[co][1] = 0ULL; }

    const float* inb = in + (size_t)b * CIN * HH * WW;

    for (int ci0 = 0; ci0 < CIN; ci0 += 4) {
        for (int idx = tid; idx < 2640; idx += 128) {
            int ci = idx / 660, rem = idx % 660;
            int hh = rem / 66, wl = rem % 66;
            int gh = h0 - 1 + hh, gw = w0 - 1 + wl;
            float v = 0.f;
            if (gh >= 0 && gh < HH && gw >= 0 && gw < WW)
                v = inb[(size_t)(ci0 + ci) * HH * WW + gh * WW + gw];
            sIn[ci][hh][wl] = v;
        }
        for (int idx = tid; idx < 288; idx += 128) {
            int co = idx / 36, rem = idx % 36, ci = rem / 9, k = rem % 9;
            float w = wgt[((size_t)(co0 + co) * CIN + ci0 + ci) * 9 + k] * sSc[co];
            sW[co][ci][k] = pack2(w, w);
        }
        __syncthreads();
#pragma unroll
        for (int ci = 0; ci < 4; ci++) {
#pragma unroll
            for (int dy = 0; dy < 3; dy++) {
#pragma unroll
                for (int dx = 0; dx < 3; dx++) {
                    float iv0 = sIn[ci][yy + dy][xx + dx];
                    float iv1 = sIn[ci][yy + dy][xx + 16 + dx];
                    float iv2 = sIn[ci][yy + dy][xx + 32 + dx];
                    float iv3 = sIn[ci][yy + dy][xx + 48 + dx];
                    u64 a01 = pack2(iv0, iv1);
                    u64 a23 = pack2(iv2, iv3);
#pragma unroll
                    for (int co = 0; co < 8; co++) {
                        u64 wv = sW[co][ci][dy * 3 + dx];
                        fma2(acc[co][0], wv, a01);
                        fma2(acc[co][1], wv, a23);
                    }
                }
            }
        }
        __syncthreads();
    }

    if (mode == 2) {
#pragma unroll
        for (int co = 0; co < 8; co++) {
            float v[4];
            unpack2(acc[co][0], v[0], v[1]);
            unpack2(acc[co][1], v[2], v[3]);
#pragma unroll
            for (int p = 0; p < 4; p++) {
                float y = fmaxf(v[p] + sSh[co], 0.f);
                out[((size_t)(b * COUT + co0 + co) * HH + h0 + yy) * WW + w0 + xx + 16 * p] = y;
            }
        }
    } else {
#pragma unroll
        for (int co = 0; co < 8; co++) {
            float v[4];
            unpack2(acc[co][0], v[0], v[1]);
            unpack2(acc[co][1], v[2], v[3]);
#pragma unroll
            for (int p = 0; p < 4; p++) {
                float y = fmaxf(v[p] + sSh[co], 0.f);
                int bits = __float_as_int(y);  // y >= 0 -> monotone int compare
                if (mode == 0) atomicMax(&sMax[co][xx + 16 * p], bits);
                else           atomicMax(&sMax[co][yy], bits);
            }
        }
        __syncthreads();
        int* gout = (int*)out;
        if (mode == 0) {
            for (int i = tid; i < 512; i += 128) {
                int co = i >> 6, w = i & 63;
                atomicMax(&gout[(b * MIDC + co0 + co) * WW + w0 + w], sMax[co][w]);
            }
        } else {
            if (tid < 64) {
                int co = tid >> 3, h = tid & 7;
                atomicMax(&gout[(b * MIDC + co0 + co) * HH + h0 + h], sMax[co][h]);
            }
        }
    }
}

// Fused merge: r = relu( bn_p(conv3x3(s, p_w)) + bn_c1(conv1x1(x, c1_w)) )
// where s[b,c,h,w] = colmax[b,c,w] + rowmax[b,c,h] (zero outside bounds).
__global__ __launch_bounds__(128)
void merge_kernel(const float* __restrict__ x,
                  const float* __restrict__ pw, const float* __restrict__ pg,
                  const float* __restrict__ pb, const float* __restrict__ pm,
                  const float* __restrict__ pv,
                  const float* __restrict__ c1w, const float* __restrict__ c1g,
                  const float* __restrict__ c1b, const float* __restrict__ c1m,
                  const float* __restrict__ c1v)
{
    __shared__ float sCm[4][66];
    __shared__ float sRm[4][10];
    __shared__ u64 sW3[8][4][9];
    __shared__ float sIn1[4][8][65];
    __shared__ u64 sW1[8][4];
    __shared__ float sScP[8], sScC[8], sSh[8];

    const int tw = blockIdx.x & 1, th = blockIdx.x >> 1;
    const int w0 = tw * 64, h0 = th * 8;
    const int co0 = blockIdx.y * 8;
    const int b = blockIdx.z;
    const int xx = threadIdx.x, yy = threadIdx.y;
    const int tid = yy * 16 + xx;

    if (tid < 8) {
        int c = co0 + tid;
        float scp = pg[c] * rsqrtf(pv[c] + EPSV);
        float scc = c1g[c] * rsqrtf(c1v[c] + EPSV);
        sScP[tid] = scp;
        sScC[tid] = scc;
        sSh[tid] = (pb[c] - pm[c] * scp) + (c1b[c] - c1m[c] * scc);
    }
    __syncthreads();

    u64 acc[8][2];
#pragma unroll
    for (int co = 0; co < 8; co++) { acc[co][0] = 0ULL; acc[co][1] = 0ULL; }

    // ---- Phase A: 1x1 conv over x, weights pre-scaled by c1 bn scale
    const float* xb = x + (size_t)b * DIMC * HH * WW;
    for (int ci0 = 0; ci0 < DIMC; ci0 += 4) {
        for (int idx = tid; idx < 2048; idx += 128) {
            int ci = idx >> 9, rem = idx & 511;
            int hh = rem >> 6, wl = rem & 63;
            sIn1[ci][hh][wl] = xb[(size_t)(ci0 + ci) * HH * WW + (h0 + hh) * WW + w0 + wl];
        }
        if (tid < 32) {
            int co = tid >> 2, ci = tid & 3;
            float w = c1w[(size_t)(co0 + co) * DIMC + ci0 + ci] * sScC[co];
            sW1[co][ci] = pack2(w, w);
        }
        __syncthreads();
#pragma unroll
        for (int ci = 0; ci < 4; ci++) {
            float iv0 = sIn1[ci][yy][xx];
            float iv1 = sIn1[ci][yy][xx + 16];
            float iv2 = sIn1[ci][yy][xx + 32];
            float iv3 = sIn1[ci][yy][xx + 48];
            u64 a01 = pack2(iv0, iv1);
            u64 a23 = pack2(iv2, iv3);
#pragma unroll
            for (int co = 0; co < 8; co++) {
                u64 wv = sW1[co][ci];
                fma2(acc[co][0], wv, a01);
                fma2(acc[co][1], wv, a23);
            }
        }
        __syncthreads();
    }

    // ---- Phase B: 3x3 conv over s (MIDC channels), s built on the fly
    for (int ci0 = 0; ci0 < MIDC; ci0 += 4) {
        for (int idx = tid; idx < 264; idx += 128) {
            int ci = idx / 66, wl = idx % 66;
            int gw = w0 - 1 + wl;
            sCm[ci][wl] = (gw >= 0 && gw < WW) ? g_colmax[(b * MIDC + ci0 + ci) * WW + gw] : 0.f;
        }
        for (int idx = tid; idx < 40; idx += 128) {
            int ci = idx / 10, hh = idx % 10;
            int gh = h0 - 1 + hh;
            sRm[ci][hh] = (gh >= 0 && gh < HH) ? g_rowmax[(b * MIDC + ci0 + ci) * HH + gh] : 0.f;
        }
        for (int idx = tid; idx < 288; idx += 128) {
            int co = idx / 36, rem = idx % 36, ci = rem / 9, k = rem % 9;
            float w = pw[((size_t)(co0 + co) * MIDC + ci0 + ci) * 9 + k] * sScP[co];
            sW3[co][ci][k] = pack2(w, w);
        }
        __syncthreads();
#pragma unroll
        for (int ci = 0; ci < 4; ci++) {
#pragma unroll
            for (int dy = 0; dy < 3; dy++) {
                bool vh = (unsigned)(h0 + yy + dy - 1) < (unsigned)HH;
                float rmv = sRm[ci][yy + dy];
#pragma unroll
                for (int dx = 0; dx < 3; dx++) {
                    float iv[4];
#pragma unroll
                    for (int p = 0; p < 4; p++) {
                        int wl = xx + 16 * p + dx;
                        bool vw = (unsigned)(w0 + wl - 1) < (unsigned)WW;
                        iv[p] = (vh && vw) ? (sCm[ci][wl] + rmv) : 0.f;
                    }
                    u64 a01 = pack2(iv[0], iv[1]);
                    u64 a23 = pack2(iv[2], iv[3]);
#pragma unroll
                    for (int co = 0; co < 8; co++) {
                        u64 wv = sW3[co][ci][dy * 3 + dx];
                        fma2(acc[co][0], wv, a01);
                        fma2(acc[co][1], wv, a23);
                    }
                }
            }
        }
        __syncthreads();
    }

    // epilogue: residual-summed BN shift + ReLU
#pragma unroll
    for (int co = 0; co < 8; co++) {
        float v[4];
        unpack2(acc[co][0], v[0], v[1]);
        unpack2(acc[co][1], v[2], v[3]);
#pragma unroll
        for (int p = 0; p < 4; p++) {
            float y = fmaxf(v[p] + sSh[co], 0.f);
            g_r[((size_t)(b * DIMC + co0 + co) * HH + h0 + yy) * WW + w0 + xx + 16 * p] = y;
        }
    }
}

extern "C" void kernel_launch(void* const* d_in, const int* in_sizes, int n_in,
                              void* d_out, int out_size)
{
    const float* x    = (const float*)d_in[0];
    const float* p1w  = (const float*)d_in[1];
    const float* p1g  = (const float*)d_in[2];
    const float* p1b  = (const float*)d_in[3];
    const float* p1m  = (const float*)d_in[4];
    const float* p1v  = (const float*)d_in[5];
    const float* p2w  = (const float*)d_in[6];
    const float* p2g  = (const float*)d_in[7];
    const float* p2b  = (const float*)d_in[8];
    const float* p2m  = (const float*)d_in[9];
    const float* p2v  = (const float*)d_in[10];
    const float* pw   = (const float*)d_in[11];
    const float* pg   = (const float*)d_in[12];
    const float* pb   = (const float*)d_in[13];
    const float* pm   = (const float*)d_in[14];
    const float* pv   = (const float*)d_in[15];
    const float* c1w  = (const float*)d_in[16];
    const float* c1g  = (const float*)d_in[17];
    const float* c1b  = (const float*)d_in[18];
    const float* c1m  = (const float*)d_in[19];
    const float* c1v  = (const float*)d_in[20];
    const float* c2w  = (const float*)d_in[21];
    const float* c2g  = (const float*)d_in[22];
    const float* c2b  = (const float*)d_in[23];
    const float* c2m  = (const float*)d_in[24];
    const float* c2v  = (const float*)d_in[25];

    float* colmax;  cudaGetSymbolAddress((void**)&colmax, g_colmax);
    float* rowmax;  cudaGetSymbolAddress((void**)&rowmax, g_rowmax);
    float* rbuf;    cudaGetSymbolAddress((void**)&rbuf, g_r);

    dim3 blk(16, 8);

    init_max_kernel<<<256, 256>>>();

    conv3_kernel<<<dim3(32, MIDC / 8, BATCH), blk>>>(
        x, p1w, p1g, p1b, p1m, p1v, DIMC, MIDC, 0, colmax);

    conv3_kernel<<<dim3(32, MIDC / 8, BATCH), blk>>>(
        x, p2w, p2g, p2b, p2m, p2v, DIMC, MIDC, 1, rowmax);

    merge_kernel<<<dim3(32, DIMC / 8, BATCH), blk>>>(
        x, pw, pg, pb, pm, pv, c1w, c1g, c1b, c1m, c1v);

    conv3_kernel<<<dim3(32, DIMC / 8, BATCH), blk>>>(
        rbuf, c2w, c2g, c2b, c2m, c2v, DIMC, DIMC, 2, (float*)d_out);
}